// round 2
// baseline (speedup 1.0000x reference)
#include <cuda_runtime.h>
#include <cstdint>

#define BB 8
#define EE 2048
#define NN 2048
#define FF 128

// Scratch for Y = X @ W^T  (8 MiB)
__device__ float g_Y[BB * NN * FF];

// ---------------- helpers ----------------
__device__ __forceinline__ uint32_t f2tf32(float x) {
    uint32_t r;
    asm("cvt.rna.tf32.f32 %0, %1;" : "=r"(r) : "f"(x));
    return r;
}

__device__ __forceinline__ void mma_tf32(float d[4], const uint32_t a[4],
                                         const uint32_t b[2], const float c[4]) {
    asm volatile(
        "mma.sync.aligned.m16n8k8.row.col.f32.tf32.tf32.f32 "
        "{%0,%1,%2,%3}, {%4,%5,%6,%7}, {%8,%9}, {%10,%11,%12,%13};"
        : "=f"(d[0]), "=f"(d[1]), "=f"(d[2]), "=f"(d[3])
        : "r"(a[0]), "r"(a[1]), "r"(a[2]), "r"(a[3]),
          "r"(b[0]), "r"(b[1]),
          "f"(c[0]), "f"(c[1]), "f"(c[2]), "f"(c[3]));
}

__device__ __forceinline__ void cpa16(uint32_t s, const void* g) {
    asm volatile("cp.async.cg.shared.global [%0], [%1], 16;" :: "r"(s), "l"(g));
}
__device__ __forceinline__ void cpa_commit() { asm volatile("cp.async.commit_group;"); }
template <int W> __device__ __forceinline__ void cpa_wait() {
    asm volatile("cp.async.wait_group %0;" :: "n"(W));
}

// ---------------- Kernel A: Y = X @ W^T ----------------
// X: [B*N, 128] row-major, W: [128, 128] row-major (torch Linear weight),
// Y[r,f] = sum_k X[r,k] * W[f,k].
// CTA tile: 128 rows x 128 cols, K=128 fully resident in smem.
// smem: sX[128][132], sW[128][132]  (stride 132 -> conflict-free frag loads)
#define A_SMEM_BYTES (2 * 128 * 132 * 4)

__global__ __launch_bounds__(256) void k_xw(const float* __restrict__ X,
                                            const float* __restrict__ W) {
    extern __shared__ float sm[];
    float* sX = sm;               // [128][132]
    float* sW = sm + 128 * 132;   // [128][132]
    const int tid = threadIdx.x;
    const long rbase = (long)blockIdx.x * 128;

    uint32_t sXb = (uint32_t)__cvta_generic_to_shared(sX);
    uint32_t sWb = (uint32_t)__cvta_generic_to_shared(sW);

#pragma unroll
    for (int i = 0; i < 16; ++i) {
        int id = tid + i * 256;        // 0..4095
        int r = id >> 5;
        int c4 = (id & 31) * 4;
        cpa16(sXb + (uint32_t)(r * 132 + c4) * 4, X + (rbase + r) * FF + c4);
        cpa16(sWb + (uint32_t)(r * 132 + c4) * 4, W + r * FF + c4);
    }
    cpa_commit();
    cpa_wait<0>();
    __syncthreads();

    const int lane = tid & 31, warp = tid >> 5;
    const int wm = warp & 3, wn = warp >> 2;
    const int gid = lane >> 2, tig = lane & 3;

    float acc[2][8][4];
#pragma unroll
    for (int mt = 0; mt < 2; ++mt)
#pragma unroll
        for (int nt = 0; nt < 8; ++nt)
#pragma unroll
            for (int j = 0; j < 4; ++j) acc[mt][nt][j] = 0.f;

#pragma unroll
    for (int ks = 0; ks < 16; ++ks) {
        const int k0 = ks * 8;
        uint32_t af[2][4];
#pragma unroll
        for (int mt = 0; mt < 2; ++mt) {
            int r = wm * 32 + mt * 16 + gid;
            af[mt][0] = f2tf32(sX[r * 132 + k0 + tig]);
            af[mt][1] = f2tf32(sX[(r + 8) * 132 + k0 + tig]);
            af[mt][2] = f2tf32(sX[r * 132 + k0 + tig + 4]);
            af[mt][3] = f2tf32(sX[(r + 8) * 132 + k0 + tig + 4]);
        }
        uint32_t bf[8][2];
#pragma unroll
        for (int nt = 0; nt < 8; ++nt) {
            int f = wn * 64 + nt * 8 + gid;   // B[k][n] = W[n][k]
            bf[nt][0] = f2tf32(sW[f * 132 + k0 + tig]);
            bf[nt][1] = f2tf32(sW[f * 132 + k0 + tig + 4]);
        }
#pragma unroll
        for (int mt = 0; mt < 2; ++mt)
#pragma unroll
            for (int nt = 0; nt < 8; ++nt)
                mma_tf32(acc[mt][nt], af[mt], bf[nt], acc[mt][nt]);
    }

    // store Y (fp32)
#pragma unroll
    for (int mt = 0; mt < 2; ++mt)
#pragma unroll
        for (int h = 0; h < 2; ++h) {
            int r = wm * 32 + mt * 16 + gid + 8 * h;
#pragma unroll
            for (int nt = 0; nt < 8; ++nt) {
                int c = wn * 64 + nt * 8 + 2 * tig;
                float2 v = make_float2(acc[mt][nt][2 * h + 0], acc[mt][nt][2 * h + 1]);
                *(float2*)&g_Y[(rbase + r) * FF + c] = v;
            }
        }
}

// ---------------- Kernel B: out = relu((mask(adj) @ Y) / cnt + b) ----------------
// CTA tile: 128 hyperedges x 128 features, K-loop over N=2048 in chunks of 32,
// double-buffered cp.async. Mask conversion (adj == -1) done at fragment load.
// Row counts accumulated from the same smem adj tiles.
// smem floats: sAdj 2*128*36 = 9216, sY 2*32*136 = 8704, cnt 128, bias 128.
#define B_SMEM_FLOATS (9216 + 8704 + 128 + 128)
#define B_SMEM_BYTES (B_SMEM_FLOATS * 4)

__global__ __launch_bounds__(256) void k_agg(const float* __restrict__ adj,
                                             const float* __restrict__ bias,
                                             float* __restrict__ out) {
    extern __shared__ float sm[];
    float* sAdj = sm;                 // [2][128][36]
    float* sY   = sm + 9216;          // [2][32][136]
    float* sCnt = sm + 9216 + 8704;   // [128]
    float* sBias = sCnt + 128;        // [128]

    const int tid = threadIdx.x;
    const int eb = blockIdx.x * 128;
    const int b = blockIdx.y;
    const float* adjBase = adj + ((long)b * EE + eb) * NN;
    const float* Yb = g_Y + (long)b * NN * FF;

    if (tid < 128) {
        sCnt[tid] = 0.f;
        sBias[tid] = bias[tid];
    }

    uint32_t sAdjb = (uint32_t)__cvta_generic_to_shared(sAdj);
    uint32_t sYb = (uint32_t)__cvta_generic_to_shared(sY);

    auto loadStage = [&](int kc, int buf) {
        const float* ap = adjBase + kc * 32;
        const float* yp = Yb + (long)kc * 32 * FF;
        uint32_t sa = sAdjb + (uint32_t)buf * (128 * 36 * 4);
        uint32_t sy = sYb + (uint32_t)buf * (32 * 136 * 4);
#pragma unroll
        for (int i = 0; i < 4; ++i) {
            int id = tid + i * 256;        // adj: 1024 x 16B
            int r = id >> 3;
            int c4 = (id & 7) * 4;
            cpa16(sa + (uint32_t)(r * 36 + c4) * 4, ap + (long)r * NN + c4);
        }
#pragma unroll
        for (int i = 0; i < 4; ++i) {
            int id = tid + i * 256;        // Y: 1024 x 16B
            int k = id >> 5;
            int c4 = (id & 31) * 4;
            cpa16(sy + (uint32_t)(k * 136 + c4) * 4, yp + k * FF + c4);
        }
    };

    const int lane = tid & 31, warp = tid >> 5;
    const int wm = warp & 3, wn = warp >> 2;
    const int gid = lane >> 2, tig = lane & 3;
    const int crow = tid >> 1, coff = (tid & 1) * 16;

    float acc[2][8][4];
#pragma unroll
    for (int mt = 0; mt < 2; ++mt)
#pragma unroll
        for (int nt = 0; nt < 8; ++nt)
#pragma unroll
            for (int j = 0; j < 4; ++j) acc[mt][nt][j] = 0.f;
    float cntLocal = 0.f;

    loadStage(0, 0);
    cpa_commit();

#pragma unroll 1
    for (int kc = 0; kc < NN / 32; ++kc) {
        const int cur = kc & 1;
        if (kc + 1 < NN / 32) {
            loadStage(kc + 1, cur ^ 1);
            cpa_commit();
            cpa_wait<1>();
        } else {
            cpa_wait<0>();
        }
        __syncthreads();

        const float* aT = sAdj + cur * (128 * 36);
        const float* yT = sY + cur * (32 * 136);

#pragma unroll
        for (int ks = 0; ks < 4; ++ks) {
            const int k0 = ks * 8;
            uint32_t af[2][4];
#pragma unroll
            for (int mt = 0; mt < 2; ++mt) {
                int r = wm * 32 + mt * 16 + gid;
                float a0 = aT[r * 36 + k0 + tig];
                float a1 = aT[(r + 8) * 36 + k0 + tig];
                float a2 = aT[r * 36 + k0 + tig + 4];
                float a3 = aT[(r + 8) * 36 + k0 + tig + 4];
                af[mt][0] = (a0 == -1.f) ? 0x3f800000u : 0u;
                af[mt][1] = (a1 == -1.f) ? 0x3f800000u : 0u;
                af[mt][2] = (a2 == -1.f) ? 0x3f800000u : 0u;
                af[mt][3] = (a3 == -1.f) ? 0x3f800000u : 0u;
            }
            uint32_t bf[8][2];
#pragma unroll
            for (int nt = 0; nt < 8; ++nt) {
                int f = wn * 64 + nt * 8 + gid;
                bf[nt][0] = f2tf32(yT[(k0 + tig) * 136 + f]);
                bf[nt][1] = f2tf32(yT[(k0 + tig + 4) * 136 + f]);
            }
#pragma unroll
            for (int mt = 0; mt < 2; ++mt)
#pragma unroll
                for (int nt = 0; nt < 8; ++nt)
                    mma_tf32(acc[mt][nt], af[mt], bf[nt], acc[mt][nt]);
        }

        // per-row membership count from the same adj tile (2 threads / row)
#pragma unroll
        for (int c = 0; c < 16; c += 4) {
            float4 v = *(const float4*)&aT[crow * 36 + coff + c];
            cntLocal += (v.x == -1.f) ? 1.f : 0.f;
            cntLocal += (v.y == -1.f) ? 1.f : 0.f;
            cntLocal += (v.z == -1.f) ? 1.f : 0.f;
            cntLocal += (v.w == -1.f) ? 1.f : 0.f;
        }
        __syncthreads();
    }

    atomicAdd(&sCnt[crow], cntLocal);
    __syncthreads();

    // epilogue: scale by 1/cnt (cnt==0 -> 1), add bias, relu
#pragma unroll
    for (int mt = 0; mt < 2; ++mt)
#pragma unroll
        for (int h = 0; h < 2; ++h) {
            int r = wm * 32 + mt * 16 + gid + 8 * h;
            float cnt = sCnt[r];
            float inv = (cnt > 0.f) ? (1.f / cnt) : 1.f;
#pragma unroll
            for (int nt = 0; nt < 8; ++nt) {
                int c = wn * 64 + nt * 8 + 2 * tig;
                float v0 = fmaxf(acc[mt][nt][2 * h + 0] * inv + sBias[c], 0.f);
                float v1 = fmaxf(acc[mt][nt][2 * h + 1] * inv + sBias[c + 1], 0.f);
                *(float2*)&out[((long)b * EE + eb + r) * FF + c] = make_float2(v0, v1);
            }
        }
}

// ---------------- launch ----------------
extern "C" void kernel_launch(void* const* d_in, const int* in_sizes, int n_in,
                              void* d_out, int out_size) {
    const float* X = (const float*)d_in[0];     // node_embeddings [B,N,F]
    const float* adj = (const float*)d_in[1];   // adj [B,E,N]
    const float* W = (const float*)d_in[2];     // W [F,F]
    const float* bias = (const float*)d_in[3];  // b [F]
    float* out = (float*)d_out;

    cudaFuncSetAttribute(k_xw, cudaFuncAttributeMaxDynamicSharedMemorySize, A_SMEM_BYTES);
    cudaFuncSetAttribute(k_agg, cudaFuncAttributeMaxDynamicSharedMemorySize, B_SMEM_BYTES);

    k_xw<<<(BB * NN) / 128, 256, A_SMEM_BYTES>>>(X, W);
    k_agg<<<dim3(EE / 128, BB), 256, B_SMEM_BYTES>>>(adj, bias, out);
}

// round 6
// speedup vs baseline: 1.3192x; 1.3192x over previous
#include <cuda_runtime.h>
#include <cstdint>

#define BB 8
#define EE 2048
#define NN 2048
#define FF 128

// Y scratch: [b][n][f], values pre-converted to tf32 bit patterns (8 MiB)
__device__ float g_Y[BB * NN * FF];

// ---------------- helpers ----------------
__device__ __forceinline__ uint32_t f2tf32(float x) {
    uint32_t r;
    asm("cvt.rna.tf32.f32 %0, %1;" : "=r"(r) : "f"(x));
    return r;
}

__device__ __forceinline__ void mma_tf32(float d[4], const uint32_t a[4],
                                         const uint32_t b[2], const float c[4]) {
    asm volatile(
        "mma.sync.aligned.m16n8k8.row.col.f32.tf32.tf32.f32 "
        "{%0,%1,%2,%3}, {%4,%5,%6,%7}, {%8,%9}, {%10,%11,%12,%13};"
        : "=f"(d[0]), "=f"(d[1]), "=f"(d[2]), "=f"(d[3])
        : "r"(a[0]), "r"(a[1]), "r"(a[2]), "r"(a[3]),
          "r"(b[0]), "r"(b[1]),
          "f"(c[0]), "f"(c[1]), "f"(c[2]), "f"(c[3]));
}

__device__ __forceinline__ void cpa16(uint32_t s, const void* g) {
    asm volatile("cp.async.cg.shared.global [%0], [%1], 16;" :: "r"(s), "l"(g));
}
__device__ __forceinline__ void cpa_commit() { asm volatile("cp.async.commit_group;"); }
template <int W> __device__ __forceinline__ void cpa_wait() {
    asm volatile("cp.async.wait_group %0;" :: "n"(W));
}

// ---------------- Kernel A: Y = tf32(X @ W^T) ----------------
// CTA tile: 64 node-rows x 128 f-cols, K=128 resident. grid = 256.
// smem: sX[64][132], sW[128][132]
#define A_SMEM_BYTES ((64 + 128) * 132 * 4)

__global__ __launch_bounds__(256, 2) void k_xw(const float* __restrict__ X,
                                               const float* __restrict__ W) {
    extern __shared__ float sm[];
    float* sX = sm;              // [64][132]
    float* sW = sm + 64 * 132;   // [128][132]
    const int tid = threadIdx.x;
    const long rbase = (long)blockIdx.x * 64;

    uint32_t sXb = (uint32_t)__cvta_generic_to_shared(sX);
    uint32_t sWb = (uint32_t)__cvta_generic_to_shared(sW);

#pragma unroll
    for (int i = 0; i < 8; ++i) {         // X: 64*128 floats = 2048 x 16B
        int id = tid + i * 256;
        int r = id >> 5;
        int c4 = (id & 31) * 4;
        cpa16(sXb + (uint32_t)(r * 132 + c4) * 4, X + (rbase + r) * FF + c4);
    }
#pragma unroll
    for (int i = 0; i < 16; ++i) {        // W: 128*128 floats = 4096 x 16B
        int id = tid + i * 256;
        int r = id >> 5;
        int c4 = (id & 31) * 4;
        cpa16(sWb + (uint32_t)(r * 132 + c4) * 4, W + r * FF + c4);
    }
    cpa_commit();
    cpa_wait<0>();
    __syncthreads();

    const int lane = tid & 31, warp = tid >> 5;
    const int wm = warp & 1, wn = warp >> 1;      // 2 M-warps x 4 N-warps
    const int gid = lane >> 2, tig = lane & 3;

    float acc[2][4][4];
#pragma unroll
    for (int mt = 0; mt < 2; ++mt)
#pragma unroll
        for (int nt = 0; nt < 4; ++nt)
#pragma unroll
            for (int j = 0; j < 4; ++j) acc[mt][nt][j] = 0.f;

#pragma unroll
    for (int ks = 0; ks < 16; ++ks) {
        const int k0 = ks * 8;
        uint32_t af[2][4];
#pragma unroll
        for (int mt = 0; mt < 2; ++mt) {          // A rows = nodes, from sX
            int r = wm * 32 + mt * 16 + gid;
            af[mt][0] = f2tf32(sX[r * 132 + k0 + tig]);
            af[mt][1] = f2tf32(sX[(r + 8) * 132 + k0 + tig]);
            af[mt][2] = f2tf32(sX[r * 132 + k0 + tig + 4]);
            af[mt][3] = f2tf32(sX[(r + 8) * 132 + k0 + tig + 4]);
        }
        uint32_t bf[4][2];
#pragma unroll
        for (int nt = 0; nt < 4; ++nt) {          // B rows = f, from sW
            int f = wn * 32 + nt * 8 + gid;
            bf[nt][0] = f2tf32(sW[f * 132 + k0 + tig]);
            bf[nt][1] = f2tf32(sW[f * 132 + k0 + tig + 4]);
        }
#pragma unroll
        for (int mt = 0; mt < 2; ++mt)
#pragma unroll
            for (int nt = 0; nt < 4; ++nt)
                mma_tf32(acc[mt][nt], af[mt], bf[nt], acc[mt][nt]);
    }

    // store Y pre-converted to tf32 bit patterns
#pragma unroll
    for (int mt = 0; mt < 2; ++mt)
#pragma unroll
        for (int h = 0; h < 2; ++h) {
            int r = wm * 32 + mt * 16 + gid + 8 * h;
#pragma unroll
            for (int nt = 0; nt < 4; ++nt) {
                int c = wn * 32 + nt * 8 + 2 * tig;
                float2 v;
                v.x = __uint_as_float(f2tf32(acc[mt][nt][2 * h + 0]));
                v.y = __uint_as_float(f2tf32(acc[mt][nt][2 * h + 1]));
                *(float2*)&g_Y[(rbase + r) * FF + c] = v;
            }
        }
}

// ---------------- Kernel B: out = relu((mask(adj) @ Y)/cnt + b) ----------------
// CTA tile: 64 edges x 128 feats, KC=32 per chunk, double-buffered.
// Mask converted once at producer (LDG -> cmp -> STS of tf32-ready bits).
// smem floats: sAdj[2][64][36]=4608, sY[2][32][136]=8704, cnt 64, bias 128.
#define B_SMEM_FLOATS (4608 + 8704 + 64 + 128)
#define B_SMEM_BYTES (B_SMEM_FLOATS * 4)

__global__ __launch_bounds__(256, 2) void k_agg(const float* __restrict__ adj,
                                                const float* __restrict__ bias,
                                                float* __restrict__ out) {
    extern __shared__ float sm[];
    float* sAdj = sm;                    // [2][64][36]
    float* sY   = sm + 4608;             // [2][32][136]
    float* sCnt = sm + 4608 + 8704;      // [64]
    float* sBias = sCnt + 64;            // [128]

    const int tid = threadIdx.x;
    const int eb = blockIdx.x * 64;
    const int b = blockIdx.y;
    const float* adjBase = adj + ((long)b * EE + eb) * NN;
    const float* Yb = g_Y + (long)b * NN * FF;

    if (tid < 64) sCnt[tid] = 0.f;
    if (tid < 128) sBias[tid] = bias[tid];

    uint32_t sAdjb = (uint32_t)__cvta_generic_to_shared(sAdj);
    uint32_t sYb = (uint32_t)__cvta_generic_to_shared(sY);

    // producer indices: each thread owns row r, cols c8..c8+7 of the adj chunk
    const int pr = tid >> 2;            // 0..63
    const int pc8 = (tid & 3) * 8;      // 0,8,16,24

    const int lane = tid & 31, warp = tid >> 5;
    const int wm = warp & 1, wn = warp >> 1;      // 2 M-warps x 4 N-warps
    const int gid = lane >> 2, tig = lane & 3;

    float acc[2][4][4];
#pragma unroll
    for (int mt = 0; mt < 2; ++mt)
#pragma unroll
        for (int nt = 0; nt < 4; ++nt)
#pragma unroll
            for (int j = 0; j < 4; ++j) acc[mt][nt][j] = 0.f;
    uint32_t cntLocal = 0;

    float4 rcur0, rcur1, rnxt0, rnxt1;

    auto ldY = [&](int s, int buf) {
        const float* yp = Yb + (long)s * 32 * FF;
        uint32_t sy = sYb + (uint32_t)buf * (32 * 136 * 4);
#pragma unroll
        for (int i = 0; i < 4; ++i) {       // 32*128 floats = 1024 x 16B
            int id = tid + i * 256;
            int k = id >> 5;
            int c4 = (id & 31) * 4;
            cpa16(sy + (uint32_t)(k * 136 + c4) * 4, yp + k * FF + c4);
        }
    };

    // prologue: stage 0
    {
        const float* ap = adjBase + (long)pr * NN + pc8;
        rcur0 = *(const float4*)(ap);
        rcur1 = *(const float4*)(ap + 4);
        ldY(0, 0);
        cpa_commit();
    }

#pragma unroll 1
    for (int s = 0; s < NN / 32; ++s) {
        const int buf = s & 1;
        if (s + 1 < NN / 32) {
            const float* ap = adjBase + (long)(s + 1) * 32 + (long)pr * NN + pc8;
            rnxt0 = *(const float4*)(ap);
            rnxt1 = *(const float4*)(ap + 4);
            ldY(s + 1, buf ^ 1);
            cpa_commit();
            cpa_wait<1>();
        } else {
            cpa_wait<0>();
        }

        // mask STS (tf32-ready bits) + count (bit 23 of 0x3f800000)
        {
            uint32_t sa = sAdjb + (uint32_t)(buf * (64 * 36) + pr * 36 + pc8) * 4;
            uint32_t m0 = (rcur0.x == -1.f) ? 0x3f800000u : 0u;
            uint32_t m1 = (rcur0.y == -1.f) ? 0x3f800000u : 0u;
            uint32_t m2 = (rcur0.z == -1.f) ? 0x3f800000u : 0u;
            uint32_t m3 = (rcur0.w == -1.f) ? 0x3f800000u : 0u;
            uint32_t m4 = (rcur1.x == -1.f) ? 0x3f800000u : 0u;
            uint32_t m5 = (rcur1.y == -1.f) ? 0x3f800000u : 0u;
            uint32_t m6 = (rcur1.z == -1.f) ? 0x3f800000u : 0u;
            uint32_t m7 = (rcur1.w == -1.f) ? 0x3f800000u : 0u;
            cntLocal += ((m0 >> 23) & 1) + ((m1 >> 23) & 1) +
                        ((m2 >> 23) & 1) + ((m3 >> 23) & 1) +
                        ((m4 >> 23) & 1) + ((m5 >> 23) & 1) +
                        ((m6 >> 23) & 1) + ((m7 >> 23) & 1);
            asm volatile("st.shared.v4.b32 [%0], {%1,%2,%3,%4};"
                         :: "r"(sa), "r"(m0), "r"(m1), "r"(m2), "r"(m3));
            asm volatile("st.shared.v4.b32 [%0], {%1,%2,%3,%4};"
                         :: "r"(sa + 16), "r"(m4), "r"(m5), "r"(m6), "r"(m7));
        }
        __syncthreads();

        const float* aT = sAdj + buf * (64 * 36);
        const uint32_t* yT = (const uint32_t*)(sY + buf * (32 * 136));

#pragma unroll
        for (int ks = 0; ks < 4; ++ks) {
            const int k0 = ks * 8;
            uint32_t af[2][4];
#pragma unroll
            for (int mt = 0; mt < 2; ++mt) {
                int r = wm * 32 + mt * 16 + gid;
                af[mt][0] = __float_as_uint(aT[r * 36 + k0 + tig]);
                af[mt][1] = __float_as_uint(aT[(r + 8) * 36 + k0 + tig]);
                af[mt][2] = __float_as_uint(aT[r * 36 + k0 + tig + 4]);
                af[mt][3] = __float_as_uint(aT[(r + 8) * 36 + k0 + tig + 4]);
            }
            uint32_t bf[4][2];
#pragma unroll
            for (int nt = 0; nt < 4; ++nt) {
                int f = wn * 32 + nt * 8 + gid;
                bf[nt][0] = yT[(k0 + tig) * 136 + f];
                bf[nt][1] = yT[(k0 + tig + 4) * 136 + f];
            }
#pragma unroll
            for (int mt = 0; mt < 2; ++mt)
#pragma unroll
                for (int nt = 0; nt < 4; ++nt)
                    mma_tf32(acc[mt][nt], af[mt], bf[nt], acc[mt][nt]);
        }
        __syncthreads();

        rcur0 = rnxt0;
        rcur1 = rnxt1;
    }

    atomicAdd(&sCnt[pr], (float)cntLocal);
    __syncthreads();

    // epilogue: scale by 1/cnt (cnt==0 -> 1), add bias, relu
#pragma unroll
    for (int mt = 0; mt < 2; ++mt)
#pragma unroll
        for (int h = 0; h < 2; ++h) {
            int r = wm * 32 + mt * 16 + gid + 8 * h;
            float cnt = sCnt[r];
            float inv = (cnt > 0.f) ? (1.f / cnt) : 1.f;
#pragma unroll
            for (int nt = 0; nt < 4; ++nt) {
                int c = wn * 32 + nt * 8 + 2 * tig;
                float v0 = fmaxf(acc[mt][nt][2 * h + 0] * inv + sBias[c], 0.f);
                float v1 = fmaxf(acc[mt][nt][2 * h + 1] * inv + sBias[c + 1], 0.f);
                *(float2*)&out[((long)b * EE + eb + r) * FF + c] = make_float2(v0, v1);
            }
        }
}

// ---------------- launch ----------------
extern "C" void kernel_launch(void* const* d_in, const int* in_sizes, int n_in,
                              void* d_out, int out_size) {
    const float* X = (const float*)d_in[0];     // node_embeddings [B,N,F]
    const float* adj = (const float*)d_in[1];   // adj [B,E,N]
    const float* W = (const float*)d_in[2];     // W [F,F]
    const float* bias = (const float*)d_in[3];  // b [F]
    float* out = (float*)d_out;

    cudaFuncSetAttribute(k_xw, cudaFuncAttributeMaxDynamicSharedMemorySize, A_SMEM_BYTES);
    cudaFuncSetAttribute(k_agg, cudaFuncAttributeMaxDynamicSharedMemorySize, B_SMEM_BYTES);

    k_xw<<<(BB * NN) / 64, 256, A_SMEM_BYTES>>>(X, W);
    k_agg<<<dim3(EE / 64, BB), 256, B_SMEM_BYTES>>>(adj, bias, out);
}

// round 8
// speedup vs baseline: 1.6584x; 1.2571x over previous
#include <cuda_runtime.h>
#include <cstdint>

#define BB 8
#define EE 2048
#define NN 2048
#define FF 128

// Y scratch: [b][n][c'] tf32 bit patterns, columns permuted within each 32-block:
// c' = (c & ~31) | ((c & 7) << 2) | ((c >> 3) & 3)   (8 MiB)
__device__ float g_Y[BB * NN * FF];

// ---------------- helpers ----------------
__device__ __forceinline__ uint32_t smem_u32(const void* p) {
    uint32_t a;
    asm("{ .reg .u64 t; cvta.to.shared.u64 t, %1; cvt.u32.u64 %0, t; }"
        : "=r"(a) : "l"(p));
    return a;
}
__device__ __forceinline__ uint32_t f2tf32(float x) {
    uint32_t r;
    asm("cvt.rna.tf32.f32 %0, %1;" : "=r"(r) : "f"(x));
    return r;
}
__device__ __forceinline__ void mma_tf32(float d[4], const uint32_t a[4],
                                         const uint32_t b[2], const float c[4]) {
    asm volatile(
        "mma.sync.aligned.m16n8k8.row.col.f32.tf32.tf32.f32 "
        "{%0,%1,%2,%3}, {%4,%5,%6,%7}, {%8,%9}, {%10,%11,%12,%13};"
        : "=f"(d[0]), "=f"(d[1]), "=f"(d[2]), "=f"(d[3])
        : "r"(a[0]), "r"(a[1]), "r"(a[2]), "r"(a[3]),
          "r"(b[0]), "r"(b[1]),
          "f"(c[0]), "f"(c[1]), "f"(c[2]), "f"(c[3]));
}
__device__ __forceinline__ void cpa16(uint32_t s, const void* g) {
    asm volatile("cp.async.cg.shared.global [%0], [%1], 16;" :: "r"(s), "l"(g));
}
__device__ __forceinline__ void cpa_commit() { asm volatile("cp.async.commit_group;"); }
template <int W> __device__ __forceinline__ void cpa_wait() {
    asm volatile("cp.async.wait_group %0;" :: "n"(W));
}

#define MBAR_INIT(addr, cnt) \
    asm volatile("mbarrier.init.shared.b64 [%0], %1;" :: "r"((uint32_t)(addr)), "r"((uint32_t)(cnt)) : "memory")
#define MBAR_ARRIVE(addr) \
    asm volatile("mbarrier.arrive.shared.b64 _, [%0];" :: "r"((uint32_t)(addr)) : "memory")
#define MBAR_WAIT(addr, ph) do {                                                     \
    uint32_t _a = (uint32_t)(addr), _p = (uint32_t)(ph);                             \
    asm volatile("{\n\t.reg .pred P;\n\t"                                            \
        "WL%=:\n\t"                                                                  \
        "mbarrier.try_wait.parity.acquire.cta.shared::cta.b64 P, [%0], %1, 0x989680;\n\t" \
        "@P bra.uni WD%=;\n\t"                                                       \
        "bra.uni WL%=;\n\t"                                                          \
        "WD%=:\n\t}" :: "r"(_a), "r"(_p) : "memory");                                \
} while (0)
#define CP_MBAR_ARRIVE(addr) \
    asm volatile("cp.async.mbarrier.arrive.shared::cta.b64 [%0];" :: "r"((uint32_t)(addr)) : "memory")

// ---------------- Kernel A: Y = tf32(X @ W^T), permuted columns ----------------
#define A_SMEM_BYTES ((64 + 128) * 132 * 4)

__global__ __launch_bounds__(256, 2) void k_xw(const float* __restrict__ X,
                                               const float* __restrict__ W) {
    extern __shared__ float sm[];
    float* sX = sm;              // [64][132]
    float* sW = sm + 64 * 132;   // [128][132]
    const int tid = threadIdx.x;
    const long rbase = (long)blockIdx.x * 64;

    uint32_t sXb = (uint32_t)__cvta_generic_to_shared(sX);
    uint32_t sWb = (uint32_t)__cvta_generic_to_shared(sW);

#pragma unroll
    for (int i = 0; i < 8; ++i) {
        int id = tid + i * 256;
        int r = id >> 5;
        int c4 = (id & 31) * 4;
        cpa16(sXb + (uint32_t)(r * 132 + c4) * 4, X + (rbase + r) * FF + c4);
    }
#pragma unroll
    for (int i = 0; i < 16; ++i) {
        int id = tid + i * 256;
        int r = id >> 5;
        int c4 = (id & 31) * 4;
        cpa16(sWb + (uint32_t)(r * 132 + c4) * 4, W + r * FF + c4);
    }
    cpa_commit();
    cpa_wait<0>();
    __syncthreads();

    const int lane = tid & 31, warp = tid >> 5;
    const int wm = warp & 1, wn = warp >> 1;
    const int gid = lane >> 2, tig = lane & 3;

    float acc[2][4][4];
#pragma unroll
    for (int mt = 0; mt < 2; ++mt)
#pragma unroll
        for (int nt = 0; nt < 4; ++nt)
#pragma unroll
            for (int j = 0; j < 4; ++j) acc[mt][nt][j] = 0.f;

#pragma unroll
    for (int ks = 0; ks < 16; ++ks) {
        const int k0 = ks * 8;
        uint32_t af[2][4];
#pragma unroll
        for (int mt = 0; mt < 2; ++mt) {
            int r = wm * 32 + mt * 16 + gid;
            af[mt][0] = f2tf32(sX[r * 132 + k0 + tig]);
            af[mt][1] = f2tf32(sX[(r + 8) * 132 + k0 + tig]);
            af[mt][2] = f2tf32(sX[r * 132 + k0 + tig + 4]);
            af[mt][3] = f2tf32(sX[(r + 8) * 132 + k0 + tig + 4]);
        }
        uint32_t bf[4][2];
#pragma unroll
        for (int nt = 0; nt < 4; ++nt) {
            int f = wn * 32 + nt * 8 + gid;
            bf[nt][0] = f2tf32(sW[f * 132 + k0 + tig]);
            bf[nt][1] = f2tf32(sW[f * 132 + k0 + tig + 4]);
        }
#pragma unroll
        for (int mt = 0; mt < 2; ++mt)
#pragma unroll
            for (int nt = 0; nt < 4; ++nt)
                mma_tf32(acc[mt][nt], af[mt], bf[nt], acc[mt][nt]);
    }

    // permuted store via smem (reuse sX region: 64*128 floats)
    __syncthreads();
    uint32_t* sOut = (uint32_t*)sX;
#pragma unroll
    for (int mt = 0; mt < 2; ++mt)
#pragma unroll
        for (int h = 0; h < 2; ++h) {
            int r = wm * 32 + mt * 16 + gid + 8 * h;
#pragma unroll
            for (int nt = 0; nt < 4; ++nt) {
                // original cols c0 = wn*32 + nt*8 + 2*tig, c1 = c0+1
                int cp0 = wn * 32 + 8 * tig + nt;        // perm(c0)
                sOut[r * 128 + cp0] = f2tf32(acc[mt][nt][2 * h + 0]);
                sOut[r * 128 + cp0 + 4] = f2tf32(acc[mt][nt][2 * h + 1]);  // perm(c1)
            }
        }
    __syncthreads();
#pragma unroll
    for (int i = 0; i < 8; ++i) {
        int id = tid + i * 256;
        int row = id >> 5;
        int c4 = (id & 31) * 4;
        float4 q = *(float4*)&((float*)sOut)[row * 128 + c4];
        *(float4*)&g_Y[(rbase + row) * FF + c4] = q;
    }
}

// ---------------- Kernel B: warp-specialized pipelined masked GEMM ----------------
// 384 threads: warps 0-7 = MMA consumers (64 edges x 128 feats),
//              warps 8-11 = producers (adj->bitmask ballot, Y cp.async).
// 4-stage ring: Y tile 32x136 f32 per stage + 64 bitmask words per stage.
#define STG_Y (32 * 136 * 4)                 // 17408 B
#define OFF_Y 0
#define OFF_MASK (4 * STG_Y)                 // 69632
#define OFF_FULL (OFF_MASK + 4 * 64 * 4)     // 70656
#define OFF_EMPTY (OFF_FULL + 32)            // 70688
#define B_SMEM_BYTES (OFF_EMPTY + 32)        // 70720

__global__ __launch_bounds__(384, 2) void k_agg(const float* __restrict__ adj,
                                                const float* __restrict__ bias,
                                                float* __restrict__ out) {
    extern __shared__ char smc[];
    const uint32_t sb = smem_u32(smc);
    const int tid = threadIdx.x, wid = tid >> 5, lane = tid & 31;
    const int eb = blockIdx.x * 64, b = blockIdx.y;
    const float* adjBase = adj + ((long)b * EE + eb) * NN;
    const float* Yb = g_Y + (long)b * NN * FF;

    if (tid == 0) {
#pragma unroll
        for (int i = 0; i < 4; ++i) {
            MBAR_INIT(sb + OFF_FULL + i * 8, 128);    // producers; cp.async arrivals self-balance
            MBAR_INIT(sb + OFF_EMPTY + i * 8, 256);   // consumer threads
        }
    }
    __syncthreads();

    if (wid >= 8) {
        // ===================== producer =====================
        const int p = tid - 256;            // 0..127
        const int pw = p >> 5, pl = p & 31;
        const float* arow = adjBase + (long)(pw * 16) * NN + pl;

        float v[16], vn[16];
#pragma unroll
        for (int i = 0; i < 16; ++i) v[i] = arow[(long)i * NN];   // chunk 0

#pragma unroll 1
        for (int s = 0; s < NN / 32; ++s) {
            const int slot = s & 3;
            MBAR_WAIT(sb + OFF_EMPTY + slot * 8, ((s >> 2) & 1) ^ 1);

            // Y tile via cp.async (16 KB / 128 threads = 8 x 16B each)
            const float* yp = Yb + (long)s * 32 * FF;
            uint32_t sy = sb + OFF_Y + slot * STG_Y;
#pragma unroll
            for (int i = 0; i < 8; ++i) {
                int cc = p + i * 128;
                int k = cc >> 5, c4 = (cc & 31) * 4;
                cpa16(sy + (uint32_t)(k * 136 + c4) * 4, yp + k * FF + c4);
            }
            CP_MBAR_ARRIVE(sb + OFF_FULL + slot * 8);

            // prefetch next adj chunk into regs (hide LDG latency)
            if (s + 1 < NN / 32) {
                const float* an = arow + (s + 1) * 32;
#pragma unroll
                for (int i = 0; i < 16; ++i) vn[i] = an[(long)i * NN];
            }

            // ballot rows into bitmasks
#pragma unroll
            for (int i = 0; i < 16; ++i) {
                uint32_t m = __ballot_sync(0xffffffffu, v[i] == -1.f);
                if (pl == i)
                    *(uint32_t*)(smc + OFF_MASK + (slot * 64 + pw * 16 + i) * 4) = m;
            }
            MBAR_ARRIVE(sb + OFF_FULL + slot * 8);

#pragma unroll
            for (int i = 0; i < 16; ++i) v[i] = vn[i];
        }
    } else {
        // ===================== consumer =====================
        const int wm = wid & 1, wn = wid >> 1;       // 2 M-warps x 4 N-warps
        const int gid = lane >> 2, tig = lane & 3;

        float acc[2][4][4];
#pragma unroll
        for (int mt = 0; mt < 2; ++mt)
#pragma unroll
            for (int nt = 0; nt < 4; ++nt)
#pragma unroll
                for (int j = 0; j < 4; ++j) acc[mt][nt][j] = 0.f;
        int cnt[4] = {0, 0, 0, 0};

#pragma unroll 1
        for (int s = 0; s < NN / 32; ++s) {
            const int slot = s & 3;
            MBAR_WAIT(sb + OFF_FULL + slot * 8, (s >> 2) & 1);

            uint32_t rm[4];
#pragma unroll
            for (int j = 0; j < 4; ++j) {
                rm[j] = *(const uint32_t*)(smc + OFF_MASK +
                                           (slot * 64 + wm * 32 + gid + 8 * j) * 4);
                cnt[j] += __popc(rm[j]);
            }

            const uint32_t yb = sb + OFF_Y + slot * STG_Y;
#pragma unroll
            for (int ks = 0; ks < 4; ++ks) {
                const int k0 = ks * 8;
                const int p0 = k0 + tig, p1 = p0 + 4;
                uint32_t b0[4], b1[4];
                asm volatile("ld.shared.v4.b32 {%0,%1,%2,%3}, [%4];"
                             : "=r"(b0[0]), "=r"(b0[1]), "=r"(b0[2]), "=r"(b0[3])
                             : "r"(yb + (uint32_t)(p0 * 136 + wn * 32 + gid * 4) * 4));
                asm volatile("ld.shared.v4.b32 {%0,%1,%2,%3}, [%4];"
                             : "=r"(b1[0]), "=r"(b1[1]), "=r"(b1[2]), "=r"(b1[3])
                             : "r"(yb + (uint32_t)(p1 * 136 + wn * 32 + gid * 4) * 4));
#pragma unroll
                for (int mt = 0; mt < 2; ++mt) {
                    // expand mask bits to tf32 1.0f (0x3f800000), NOT 1<<23 (denormal!)
                    uint32_t af[4];
                    af[0] = (0u - ((rm[2 * mt] >> p0) & 1u)) & 0x3f800000u;
                    af[1] = (0u - ((rm[2 * mt + 1] >> p0) & 1u)) & 0x3f800000u;
                    af[2] = (0u - ((rm[2 * mt] >> p1) & 1u)) & 0x3f800000u;
                    af[3] = (0u - ((rm[2 * mt + 1] >> p1) & 1u)) & 0x3f800000u;
#pragma unroll
                    for (int nt = 0; nt < 4; ++nt) {
                        uint32_t bf[2] = {b0[nt], b1[nt]};
                        mma_tf32(acc[mt][nt], af, bf, acc[mt][nt]);
                    }
                }
            }
            MBAR_ARRIVE(sb + OFF_EMPTY + slot * 8);
        }

        // epilogue: counts live in regs (cnt[2*mt+h] = row wm*32+mt*16+gid+8h)
#pragma unroll
        for (int mt = 0; mt < 2; ++mt)
#pragma unroll
            for (int h = 0; h < 2; ++h) {
                int r = wm * 32 + mt * 16 + gid + 8 * h;
                float c = (float)cnt[2 * mt + h];
                float inv = (c > 0.f) ? (1.f / c) : 1.f;
#pragma unroll
                for (int nt = 0; nt < 4; ++nt) {
                    int cidx = wn * 32 + nt * 8 + 2 * tig;
                    float2 bv = *(const float2*)&bias[cidx];
                    float v0 = fmaxf(acc[mt][nt][2 * h + 0] * inv + bv.x, 0.f);
                    float v1 = fmaxf(acc[mt][nt][2 * h + 1] * inv + bv.y, 0.f);
                    *(float2*)&out[((long)b * EE + eb + r) * FF + cidx] =
                        make_float2(v0, v1);
                }
            }
    }
}

// ---------------- launch ----------------
extern "C" void kernel_launch(void* const* d_in, const int* in_sizes, int n_in,
                              void* d_out, int out_size) {
    const float* X = (const float*)d_in[0];     // node_embeddings [B,N,F]
    const float* adj = (const float*)d_in[1];   // adj [B,E,N]
    const float* W = (const float*)d_in[2];     // W [F,F]
    const float* bias = (const float*)d_in[3];  // b [F]
    float* out = (float*)d_out;

    cudaFuncSetAttribute(k_xw, cudaFuncAttributeMaxDynamicSharedMemorySize, A_SMEM_BYTES);
    cudaFuncSetAttribute(k_agg, cudaFuncAttributeMaxDynamicSharedMemorySize, B_SMEM_BYTES);

    k_xw<<<(BB * NN) / 64, 256, A_SMEM_BYTES>>>(X, W);
    k_agg<<<dim3(EE / 64, BB), 384, B_SMEM_BYTES>>>(adj, bias, out);
}